// round 12
// baseline (speedup 1.0000x reference)
#include <cuda_runtime.h>
#include <cuda_bf16.h>
#include <cstdint>

// WeightedAverage: out = sum_{3x3} v*exp(-v) / sum_{3x3} exp(-v)
// (softmax(-(local - x^2)) == softmax(-local); zero padding == OOB v=0.)
//
// cp.async-staged row pipeline: per-warp 6-slot smem ring, wait_group 4
// -> 4 rows (2KB) in flight per warp with LOW register pressure (in-flight
// data lives in smem, decoupling MLP from regs — R9/R11 showed reg-resident
// MLP trades 1:1 against occupancy and loses). Halo scalars come from the
// staged row (LDS neighbor word; cp.async'ed edge words for lanes 0/31).
// Tiles 128x256 (8 warps x 32 rows), grid 576 = 2 tiles/block, single wave.
// Sweep fully unrolled (R6: partial unroll kills MLP).

#define IMG_W   1536
#define IMG_H   1536
#define SROWS   32
#define WPB     8
#define TILES_X 12
#define TILES_Y 6
#define N_IMG   16
#define N_TILES (TILES_X * TILES_Y * N_IMG)   // 1152
#define NBLK    576                           // exactly 2 tiles per block
#define DEPTH   6
#define SLOTF   132   // floats per slot: 128 vec + vl(128) + vr(129) + pad

__device__ __forceinline__ void cpa16(uint32_t d, const float* s) {
    asm volatile("cp.async.cg.shared.global [%0], [%1], 16;\n" :: "r"(d), "l"(s));
}
__device__ __forceinline__ void cpa4(uint32_t d, const float* s) {
    asm volatile("cp.async.ca.shared.global [%0], [%1], 4;\n" :: "r"(d), "l"(s));
}
#define CP_COMMIT() asm volatile("cp.async.commit_group;\n" ::: "memory")
#define CP_WAIT(N)  asm volatile("cp.async.wait_group %0;\n" :: "n"(N) : "memory")

__device__ __forceinline__ float4 f4add(const float4 a, const float4 b) {
    return make_float4(a.x + b.x, a.y + b.y, a.z + b.z, a.w + b.w);
}

__global__ __launch_bounds__(256, 4)
void wavg_kernel(const float* __restrict__ x, float* __restrict__ out) {
    __shared__ __align__(16) float sm[WPB][DEPTH][SLOTF];

    const int lane = threadIdx.x & 31;
    const int wrp  = threadIdx.x >> 5;
    float* const wb = &sm[wrp][0][0];

    #pragma unroll 1
    for (int t = blockIdx.x; t < N_TILES; t += NBLK) {
        const int img_i = t / (TILES_X * TILES_Y);
        const int rem   = t - img_i * (TILES_X * TILES_Y);
        const int ty    = rem / TILES_X;
        const int tx    = rem - ty * TILES_X;

        const int colw = tx * 128;              // warp band start column
        const int y0   = ty * (WPB * SROWS) + wrp * SROWS;
        const size_t ibase = (size_t)img_i * (size_t)(IMG_W * IMG_H);
        const float* __restrict__ img = x + ibase;
        float* __restrict__ optr = out + ibase + (size_t)y0 * IMG_W + colw + lane * 4;

        const bool has_l = (colw > 0);
        const bool has_r = (colw + 128 < IMG_W);

        // Drain any pending groups from the previous tile; pre-zero edge halo
        // words for slots cp.async will never write (image-border columns).
        CP_WAIT(0);
        if (lane < DEPTH) {
            if (!has_l) (wb + lane * SLOTF)[128] = 0.f;
            if (!has_r) (wb + lane * SLOTF)[129] = 0.f;
        }
        __syncwarp();

        // Stage row y into ring slot s (one commit group per row).
        auto issue_row = [&](int y, int s) {
            float* slotp = wb + s * SLOTF;
            if ((unsigned)y < (unsigned)IMG_H) {
                const float* src = img + (size_t)y * IMG_W + colw + lane * 4;
                cpa16((uint32_t)__cvta_generic_to_shared(slotp + lane * 4), src);
                if (lane == 0 && has_l)
                    cpa4((uint32_t)__cvta_generic_to_shared(slotp + 128), src - 1);
                if (lane == 31 && has_r)
                    cpa4((uint32_t)__cvta_generic_to_shared(slotp + 129), src + 4);
            } else {
                *reinterpret_cast<float4*>(slotp + lane * 4) =
                    make_float4(0.f, 0.f, 0.f, 0.f);
                if (lane == 0) { slotp[128] = 0.f; slotp[129] = 0.f; }
            }
            CP_COMMIT();
        };

        // Consume slot s: horizontal 3-sums of w=exp(-v) and wv.
        auto hsum = [&](int s, float4& w, float4& wv) {
            const float* sp = wb + s * SLOTF;
            const float4 v = *reinterpret_cast<const float4*>(sp + lane * 4);
            const float vl = (lane == 0)  ? sp[128] : sp[lane * 4 - 1];
            const float vr = (lane == 31) ? sp[129] : sp[lane * 4 + 4];
            const float w0 = __expf(-v.x);
            const float w1 = __expf(-v.y);
            const float w2 = __expf(-v.z);
            const float w3 = __expf(-v.w);
            const float wl = __expf(-vl);
            const float wr = __expf(-vr);
            w.x = wl + w0 + w1;
            w.y = w0 + w1 + w2;
            w.z = w1 + w2 + w3;
            w.w = w2 + w3 + wr;
            const float al = wl * vl, a0 = w0 * v.x, a1 = w1 * v.y;
            const float a2 = w2 * v.z, a3 = w3 * v.w, ar = wr * vr;
            wv.x = al + a0 + a1;
            wv.y = a0 + a1 + a2;
            wv.z = a1 + a2 + a3;
            wv.w = a2 + a3 + ar;
        };

        // Prologue: stage rows y0-1 .. y0+4 (slots 0..5, groups g1..g6).
        #pragma unroll
        for (int r = 0; r < DEPTH; r++)
            issue_row(y0 - 1 + r, r);
        CP_WAIT(4);           // g1,g2 done -> rows y0-1, y0 ready
        __syncwarp();

        float4 hw0, hv0, hw1, hv1;
        hsum(0, hw0, hv0);    // row y0-1
        hsum(1, hw1, hv1);    // row y0
        float4 Aw  = f4add(hw0, hw1), Bw  = hw1;   // A = h(-1)+h(0), B = h(0)
        float4 Awv = f4add(hv0, hv1), Bwv = hv1;

        #pragma unroll
        for (int k = 0; k < SROWS; k++) {
            // Stage row y0+k+5 into slot k%6 (its previous row was consumed
            // at iter k-2; ordered by the per-iter syncwarps).
            if (k < SROWS - 4)
                issue_row(y0 + k + 5, k % 6);
            else
                CP_COMMIT();  // keep group accounting uniform
            CP_WAIT(4);       // row y0+k+1 (group k+3) complete
            __syncwarp();     // make neighbors' staged bytes visible

            float4 hw, hv;
            hsum((k + 2) % 6, hw, hv);   // row y0+k+1

            const float4 den = f4add(Aw,  hw);
            const float4 num = f4add(Awv, hv);
            float4 o;
            o.x = __fdividef(num.x, den.x);
            o.y = __fdividef(num.y, den.y);
            o.z = __fdividef(num.z, den.z);
            o.w = __fdividef(num.w, den.w);
            __stcs(reinterpret_cast<float4*>(optr), o);
            optr += IMG_W;

            Aw  = f4add(Bw,  hw);  Bw  = hw;
            Awv = f4add(Bwv, hv);  Bwv = hv;
        }
    }
}

extern "C" void kernel_launch(void* const* d_in, const int* in_sizes, int n_in,
                              void* d_out, int out_size) {
    const float* x = (const float*)d_in[0];
    float* out = (float*)d_out;
    wavg_kernel<<<NBLK, WPB * 32>>>(x, out);
}

// round 13
// speedup vs baseline: 1.0734x; 1.0734x over previous
#include <cuda_runtime.h>
#include <cuda_bf16.h>

// WeightedAverage: out = sum_{3x3} v*exp(-v) / sum_{3x3} exp(-v)
// (softmax(-(local - x^2)) == softmax(-local); zero padding == OOB v=0.)
//
// R10 base (128x256 tiles, 8 warps x 32 rows, grid 592 = 148x4 single wave,
// fully-unrolled sweep, regs uncapped) with:
//  - halo columns via shfl of the already-loaded float4 at consume time
//    (data loaded 3 iters ago -> no load->shfl dependency; R2's pitfall
//    avoided). Edge lanes 0/31 use one prefetched predicated scalar.
//  - slot = {float4 v, float edge} (5 regs): 1 predicated LDG replaces two
//    all-lane scalar LDGs -> ~2x fewer L1 wavefronts, fewer issues/row.
//  - 4-slot ring, prefetch distance 3 (fits the freed registers).

#define IMG_W   1536
#define IMG_H   1536
#define SROWS   32
#define WPB     8
#define TILES_X 12
#define TILES_Y 6
#define N_IMG   16
#define N_TILES (TILES_X * TILES_Y * N_IMG)   // 1152
#define NBLK    592                           // 148 SM x 4 resident blocks

struct Slot { float4 v; float edge; };

__device__ __forceinline__ float4 f4add(const float4 a, const float4 b) {
    return make_float4(a.x + b.x, a.y + b.y, a.z + b.z, a.w + b.w);
}

__global__ __launch_bounds__(256, 4)
void wavg_kernel(const float* __restrict__ x, float* __restrict__ out) {
    const int lane = threadIdx.x & 31;
    const int wrp  = threadIdx.x >> 5;

    #pragma unroll 1
    for (int t = blockIdx.x; t < N_TILES; t += NBLK) {
        const int img_i = t / (TILES_X * TILES_Y);
        const int rem   = t - img_i * (TILES_X * TILES_Y);
        const int ty    = rem / TILES_X;
        const int tx    = rem - ty * TILES_X;

        const int col0 = tx * 128 + lane * 4;
        const int y0   = ty * (WPB * SROWS) + wrp * SROWS;
        const size_t ibase = (size_t)img_i * (size_t)(IMG_W * IMG_H);
        const float* __restrict__ img = x + ibase;
        float* __restrict__ optr = out + ibase + (size_t)y0 * IMG_W + col0;

        const bool has_l = (col0 > 0);
        const bool has_r = (col0 + 4 < IMG_W);

        Slot ring[4];

        // Load row y: float4 + one predicated edge scalar (lanes 0/31 only).
        auto loadrow = [&](int y) -> Slot {
            Slot s;
            s.v = make_float4(0.f, 0.f, 0.f, 0.f);
            s.edge = 0.f;
            if ((unsigned)y < (unsigned)IMG_H) {
                const float* p = img + (size_t)y * IMG_W + col0;
                s.v = __ldg(reinterpret_cast<const float4*>(p));
                if (lane == 0) {
                    if (has_l) s.edge = __ldg(p - 1);
                } else if (lane == 31) {
                    if (has_r) s.edge = __ldg(p + 4);
                }
            }
            return s;
        };

        // Horizontal 3-sums; halo columns from warp shuffles of v.
        auto hsum = [&](const Slot& s, float4& w, float4& wv) {
            float vl = __shfl_up_sync(0xffffffffu,  s.v.w, 1);
            float vr = __shfl_down_sync(0xffffffffu, s.v.x, 1);
            if (lane == 0)  vl = s.edge;
            if (lane == 31) vr = s.edge;
            const float w0 = __expf(-s.v.x);
            const float w1 = __expf(-s.v.y);
            const float w2 = __expf(-s.v.z);
            const float w3 = __expf(-s.v.w);
            const float wl = __expf(-vl);
            const float wr = __expf(-vr);
            w.x = wl + w0 + w1;
            w.y = w0 + w1 + w2;
            w.z = w1 + w2 + w3;
            w.w = w2 + w3 + wr;
            const float al = wl * vl,  a0 = w0 * s.v.x, a1 = w1 * s.v.y;
            const float a2 = w2 * s.v.z, a3 = w3 * s.v.w, ar = wr * vr;
            wv.x = al + a0 + a1;
            wv.y = a0 + a1 + a2;
            wv.z = a1 + a2 + a3;
            wv.w = a2 + a3 + ar;
        };

        // Prologue: rows y0-1, y0 consumed immediately; rows y0+1..y0+3 in
        // flight in slots 0..2. slot(row) = (row - y0 - 1) & 3.
        Slot s_m1 = loadrow(y0 - 1);
        Slot s_0  = loadrow(y0);
        ring[0] = loadrow(y0 + 1);
        ring[1] = loadrow(y0 + 2);
        ring[2] = loadrow(y0 + 3);

        float4 hw0, hv0, hw1, hv1;
        hsum(s_m1, hw0, hv0);
        hsum(s_0,  hw1, hv1);
        float4 Aw  = f4add(hw0, hw1), Bw  = hw1;   // A = h(-1)+h(0), B = h(0)
        float4 Awv = f4add(hv0, hv1), Bwv = hv1;

        #pragma unroll
        for (int k = 0; k < SROWS; k++) {
            // Prefetch row y0+k+4 into slot (k+3)&3 (freed at iter k-2).
            if (k < SROWS - 3)
                ring[(k + 3) & 3] = loadrow(y0 + k + 4);
            // Consume row y0+k+1 (slot k&3), loaded 3 iterations ago.
            float4 hw, hv;
            hsum(ring[k & 3], hw, hv);

            const float4 den = f4add(Aw,  hw);
            const float4 num = f4add(Awv, hv);
            float4 o;
            o.x = __fdividef(num.x, den.x);
            o.y = __fdividef(num.y, den.y);
            o.z = __fdividef(num.z, den.z);
            o.w = __fdividef(num.w, den.w);
            __stcs(reinterpret_cast<float4*>(optr), o);
            optr += IMG_W;

            Aw  = f4add(Bw,  hw);  Bw  = hw;
            Awv = f4add(Bwv, hv);  Bwv = hv;
        }
    }
}

extern "C" void kernel_launch(void* const* d_in, const int* in_sizes, int n_in,
                              void* d_out, int out_size) {
    const float* x = (const float*)d_in[0];
    float* out = (float*)d_out;
    wavg_kernel<<<NBLK, WPB * 32>>>(x, out);
}

// round 14
// speedup vs baseline: 1.1230x; 1.0462x over previous
#include <cuda_runtime.h>
#include <cuda_bf16.h>

// WeightedAverage: out = sum_{3x3} v*exp(-v) / sum_{3x3} exp(-v)
// (softmax(-(local - x^2)) == softmax(-local); zero padding == OOB v=0.)
//
// R10 structure (best: ncu 48.3us, RF-saturated at 64 regs x 4 blocks/SM):
// 1152 tiles of 128x256 (8 warps x 32 rows), grid 592 = 148x4 single wave,
// 3-slot ring {float4, vl, vr} prefetched 2 rows ahead, fully unrolled.
// This round: __ldcs (evict-first) on the streaming vector loads so the
// single-use input stream doesn't evict the 151MB write stream from L2
// (stores are __stcs). Halo scalars stay __ldg (hit the neighbor lane's
// in-flight line from the same loadrow call).

#define IMG_W   1536
#define IMG_H   1536
#define SROWS   32
#define WPB     8
#define TILES_X 12
#define TILES_Y 6
#define N_IMG   16
#define N_TILES (TILES_X * TILES_Y * N_IMG)   // 1152
#define NBLK    592                           // 148 SM x 4 resident blocks

struct Slot { float4 v; float vl, vr; };

__device__ __forceinline__ float4 f4add(const float4 a, const float4 b) {
    return make_float4(a.x + b.x, a.y + b.y, a.z + b.z, a.w + b.w);
}

__global__ __launch_bounds__(256, 4)
void wavg_kernel(const float* __restrict__ x, float* __restrict__ out) {
    const int lane = threadIdx.x & 31;
    const int wrp  = threadIdx.x >> 5;

    #pragma unroll 1
    for (int t = blockIdx.x; t < N_TILES; t += NBLK) {
        const int img_i = t / (TILES_X * TILES_Y);
        const int rem   = t - img_i * (TILES_X * TILES_Y);
        const int ty    = rem / TILES_X;
        const int tx    = rem - ty * TILES_X;

        const int col0 = tx * 128 + lane * 4;
        const int y0   = ty * 256 + wrp * SROWS;
        const size_t ibase = (size_t)img_i * (size_t)(IMG_W * IMG_H);
        const float* __restrict__ img = x + ibase;
        float* __restrict__ optr = out + ibase + (size_t)y0 * IMG_W + col0;

        const bool has_l = (col0 > 0);
        const bool has_r = (col0 + 4 < IMG_W);

        Slot ring[3];

        // Load row y: streaming float4 plus both halo scalars, together.
        auto loadrow = [&](int y) -> Slot {
            Slot s;
            s.v = make_float4(0.f, 0.f, 0.f, 0.f);
            s.vl = 0.f; s.vr = 0.f;
            if ((unsigned)y < (unsigned)IMG_H) {
                const float* p = img + (size_t)y * IMG_W + col0;
                s.v = __ldcs(reinterpret_cast<const float4*>(p));
                if (has_l) s.vl = __ldg(p - 1);
                if (has_r) s.vr = __ldg(p + 4);
            }
            return s;
        };

        // Horizontal 3-sums of w=exp(-v) and wv for one row (pure compute).
        auto hsum = [&](const Slot& s, float4& w, float4& wv) {
            const float w0 = __expf(-s.v.x);
            const float w1 = __expf(-s.v.y);
            const float w2 = __expf(-s.v.z);
            const float w3 = __expf(-s.v.w);
            const float wl = __expf(-s.vl);
            const float wr = __expf(-s.vr);
            w.x = wl + w0 + w1;
            w.y = w0 + w1 + w2;
            w.z = w1 + w2 + w3;
            w.w = w2 + w3 + wr;
            const float al = wl * s.vl,  a0 = w0 * s.v.x, a1 = w1 * s.v.y;
            const float a2 = w2 * s.v.z, a3 = w3 * s.v.w, ar = wr * s.vr;
            wv.x = al + a0 + a1;
            wv.y = a0 + a1 + a2;
            wv.z = a1 + a2 + a3;
            wv.w = a2 + a3 + ar;
        };

        // Prologue. slot(row) = (row - y0 + 2) % 3.
        Slot s_m1 = loadrow(y0 - 1);
        Slot s_0  = loadrow(y0);
        ring[0] = loadrow(y0 + 1);   // row y0+1 -> slot 0
        ring[1] = loadrow(y0 + 2);   // row y0+2 -> slot 1

        float4 hw0, hv0, hw1, hv1;
        hsum(s_m1, hw0, hv0);
        hsum(s_0,  hw1, hv1);
        float4 Aw  = f4add(hw0, hw1), Bw  = hw1;   // A = h(-1)+h(0), B = h(0)
        float4 Awv = f4add(hv0, hv1), Bwv = hv1;

        #pragma unroll
        for (int k = 0; k < SROWS; k++) {
            // Prefetch row y0+k+3 into slot (k+2)%3 (freed: row y0+k consumed
            // at k-1). Live rows k+1..k+3 occupy the 3 slots.
            if (k < SROWS - 2)
                ring[(k + 2) % 3] = loadrow(y0 + k + 3);
            // Consume row y0+k+1 (slot k%3), loaded 2 iterations ago.
            float4 hw, hv;
            hsum(ring[k % 3], hw, hv);

            const float4 den = f4add(Aw,  hw);
            const float4 num = f4add(Awv, hv);
            float4 o;
            o.x = __fdividef(num.x, den.x);
            o.y = __fdividef(num.y, den.y);
            o.z = __fdividef(num.z, den.z);
            o.w = __fdividef(num.w, den.w);
            __stcs(reinterpret_cast<float4*>(optr), o);
            optr += IMG_W;

            Aw  = f4add(Bw,  hw);  Bw  = hw;
            Awv = f4add(Bwv, hv);  Bwv = hv;
        }
    }
}

extern "C" void kernel_launch(void* const* d_in, const int* in_sizes, int n_in,
                              void* d_out, int out_size) {
    const float* x = (const float*)d_in[0];
    float* out = (float*)d_out;
    wavg_kernel<<<NBLK, WPB * 32>>>(x, out);
}

// round 15
// speedup vs baseline: 1.1450x; 1.0196x over previous
#include <cuda_runtime.h>
#include <cuda_bf16.h>

// WeightedAverage: out = sum_{3x3} v*exp(-v) / sum_{3x3} exp(-v)
// (softmax(-(local - x^2)) == softmax(-local); zero padding == OOB v=0.)
//
// R14 structure (best: ncu 48.06us; RF-saturated 64 regs x 4 blk/SM; __ldcs
// streaming reads, __stcs writes; 3-slot ring {float4, vl, vr} prefetched
// 2 rows ahead; fully unrolled sweep) with SROWS=64:
// tiles 128x512, 576 tiles = grid 576, ONE tile per block, single wave.
// Vertical halo re-read 6.25% -> 3.1% of input; tile loop + second pipeline
// warm-up eliminated. I$ grows (~2x body) but straight-line prefetch-
// overlapped miss cost << traffic saving.

#define IMG_W   1536
#define IMG_H   1536
#define SROWS   64
#define WPB     8
#define TILES_X 12
#define TILES_Y 3
#define N_IMG   16
#define NBLK    (TILES_X * TILES_Y * N_IMG)   // 576 = one tile per block

struct Slot { float4 v; float vl, vr; };

__device__ __forceinline__ float4 f4add(const float4 a, const float4 b) {
    return make_float4(a.x + b.x, a.y + b.y, a.z + b.z, a.w + b.w);
}

__global__ __launch_bounds__(256, 4)
void wavg_kernel(const float* __restrict__ x, float* __restrict__ out) {
    const int lane = threadIdx.x & 31;
    const int wrp  = threadIdx.x >> 5;

    const int t     = blockIdx.x;
    const int img_i = t / (TILES_X * TILES_Y);
    const int rem   = t - img_i * (TILES_X * TILES_Y);
    const int ty    = rem / TILES_X;
    const int tx    = rem - ty * TILES_X;

    const int col0 = tx * 128 + lane * 4;
    const int y0   = ty * (WPB * SROWS) + wrp * SROWS;
    const size_t ibase = (size_t)img_i * (size_t)(IMG_W * IMG_H);
    const float* __restrict__ img = x + ibase;
    float* __restrict__ optr = out + ibase + (size_t)y0 * IMG_W + col0;

    const bool has_l = (col0 > 0);
    const bool has_r = (col0 + 4 < IMG_W);

    Slot ring[3];

    // Load row y: streaming float4 plus both halo scalars, together.
    auto loadrow = [&](int y) -> Slot {
        Slot s;
        s.v = make_float4(0.f, 0.f, 0.f, 0.f);
        s.vl = 0.f; s.vr = 0.f;
        if ((unsigned)y < (unsigned)IMG_H) {
            const float* p = img + (size_t)y * IMG_W + col0;
            s.v = __ldcs(reinterpret_cast<const float4*>(p));
            if (has_l) s.vl = __ldg(p - 1);
            if (has_r) s.vr = __ldg(p + 4);
        }
        return s;
    };

    // Horizontal 3-sums of w=exp(-v) and wv for one row (pure compute).
    auto hsum = [&](const Slot& s, float4& w, float4& wv) {
        const float w0 = __expf(-s.v.x);
        const float w1 = __expf(-s.v.y);
        const float w2 = __expf(-s.v.z);
        const float w3 = __expf(-s.v.w);
        const float wl = __expf(-s.vl);
        const float wr = __expf(-s.vr);
        w.x = wl + w0 + w1;
        w.y = w0 + w1 + w2;
        w.z = w1 + w2 + w3;
        w.w = w2 + w3 + wr;
        const float al = wl * s.vl,  a0 = w0 * s.v.x, a1 = w1 * s.v.y;
        const float a2 = w2 * s.v.z, a3 = w3 * s.v.w, ar = wr * s.vr;
        wv.x = al + a0 + a1;
        wv.y = a0 + a1 + a2;
        wv.z = a1 + a2 + a3;
        wv.w = a2 + a3 + ar;
    };

    // Prologue. slot(row) = (row - y0 + 2) % 3.
    Slot s_m1 = loadrow(y0 - 1);
    Slot s_0  = loadrow(y0);
    ring[0] = loadrow(y0 + 1);   // row y0+1 -> slot 0
    ring[1] = loadrow(y0 + 2);   // row y0+2 -> slot 1

    float4 hw0, hv0, hw1, hv1;
    hsum(s_m1, hw0, hv0);
    hsum(s_0,  hw1, hv1);
    float4 Aw  = f4add(hw0, hw1), Bw  = hw1;   // A = h(-1)+h(0), B = h(0)
    float4 Awv = f4add(hv0, hv1), Bwv = hv1;

    #pragma unroll
    for (int k = 0; k < SROWS; k++) {
        // Prefetch row y0+k+3 into slot (k+2)%3 (freed: row y0+k consumed
        // at k-1). Live rows k+1..k+3 occupy the 3 slots.
        if (k < SROWS - 2)
            ring[(k + 2) % 3] = loadrow(y0 + k + 3);
        // Consume row y0+k+1 (slot k%3), loaded 2 iterations ago.
        float4 hw, hv;
        hsum(ring[k % 3], hw, hv);

        const float4 den = f4add(Aw,  hw);
        const float4 num = f4add(Awv, hv);
        float4 o;
        o.x = __fdividef(num.x, den.x);
        o.y = __fdividef(num.y, den.y);
        o.z = __fdividef(num.z, den.z);
        o.w = __fdividef(num.w, den.w);
        __stcs(reinterpret_cast<float4*>(optr), o);
        optr += IMG_W;

        Aw  = f4add(Bw,  hw);  Bw  = hw;
        Awv = f4add(Bwv, hv);  Bwv = hv;
    }
}

extern "C" void kernel_launch(void* const* d_in, const int* in_sizes, int n_in,
                              void* d_out, int out_size) {
    const float* x = (const float*)d_in[0];
    float* out = (float*)d_out;
    wavg_kernel<<<NBLK, WPB * 32>>>(x, out);
}